// round 1
// baseline (speedup 1.0000x reference)
#include <cuda_runtime.h>
#include <math.h>

#define NTOK 8192
#define CDIM 256
#define NHEAD 4
#define HD 64
#define QKVN 768
#define MAXDIST 4.242640687119285f  /* sqrt(18) */

// ---------------- scratch (no cudaMalloc allowed) ----------------
__device__ float g_qkv[NTOK * QKVN];      // silu(x@W_qkv)  (q|k|v)
__device__ float g_q[NTOK * CDIM];        // normed+roped q
__device__ float g_k[NTOK * CDIM];        // normed+roped k
__device__ float g_att[NTOK * CDIM];      // attention output (pre-rmsnorm)
__device__ float g_merged[NTOK * CDIM];   // gate-merged
__device__ float g_width[NTOK * NHEAD];
__device__ float g_sharp[NTOK * NHEAD];
__device__ float g_rmsinv[NTOK];

__device__ __forceinline__ float sigmoidf_(float x) { return 1.f / (1.f + __expf(-x)); }
__device__ __forceinline__ float siluf_(float x) { return x * sigmoidf_(x); }

// ---------------- tiled SGEMM 64x64x16, 256 threads, 4x4/thread ----------------
// EPI 0: C = silu(acc)
// EPI 1: gate-merge: g = sigmoid(silu(acc + bias[c]));
//        C = g * A[r*lda+c] + (1-g) * (g_att[r,c] * g_rmsinv[r] * wonorm[c])
template <int EPI>
__global__ void __launch_bounds__(256) gemm64(
    const float* __restrict__ A, int lda,
    const float* __restrict__ B, int ldb,
    float* __restrict__ Cmat, int ldc,
    const float* __restrict__ bias,
    const float* __restrict__ wonorm)
{
    __shared__ float As[16][64];   // transposed: As[k][row]
    __shared__ float Bs[16][64];   // Bs[k][col]

    int tid = threadIdx.x;
    int tx = tid & 15, ty = tid >> 4;
    int rowBase = blockIdx.y * 64;
    int colBase = blockIdx.x * 64;

    int arow = tid >> 2, ac = (tid & 3) * 4;
    int brow = tid >> 4, bc = (tid & 15) * 4;
    const float* Aptr = A + (size_t)(rowBase + arow) * lda + ac;
    const float* Bptr = B + (size_t)brow * ldb + colBase + bc;

    float acc[4][4];
#pragma unroll
    for (int i = 0; i < 4; i++)
#pragma unroll
        for (int j = 0; j < 4; j++) acc[i][j] = 0.f;

    for (int kt = 0; kt < 256; kt += 16) {
        float4 av = *(const float4*)(Aptr + kt);
        float4 bv = *(const float4*)(Bptr + (size_t)kt * ldb);
        __syncthreads();
        As[ac + 0][arow] = av.x;
        As[ac + 1][arow] = av.y;
        As[ac + 2][arow] = av.z;
        As[ac + 3][arow] = av.w;
        *(float4*)&Bs[brow][bc] = bv;
        __syncthreads();
#pragma unroll
        for (int k = 0; k < 16; k++) {
            float4 a = *(float4*)&As[k][ty * 4];
            float4 b = *(float4*)&Bs[k][tx * 4];
            float ar[4] = {a.x, a.y, a.z, a.w};
            float br[4] = {b.x, b.y, b.z, b.w};
#pragma unroll
            for (int i = 0; i < 4; i++)
#pragma unroll
                for (int j = 0; j < 4; j++) acc[i][j] += ar[i] * br[j];
        }
    }

#pragma unroll
    for (int i = 0; i < 4; i++) {
        int r = rowBase + ty * 4 + i;
#pragma unroll
        for (int j = 0; j < 4; j++) {
            int c = colBase + tx * 4 + j;
            float val = acc[i][j];
            if (EPI == 0) {
                Cmat[(size_t)r * ldc + c] = siluf_(val);
            } else {
                float t = val + bias[c];
                float g = sigmoidf_(siluf_(t));
                float vv = A[(size_t)r * lda + c];
                float att = g_att[(size_t)r * CDIM + c] * g_rmsinv[r] * wonorm[c];
                Cmat[(size_t)r * ldc + c] = g * vv + (1.f - g) * att;
            }
        }
    }
}

// ---------------- fused rmsnorm + RoPE (pos = head index!) + width/sharp ----------------
// warp per token; lane l holds channels [l*8, l*8+8)
__global__ void __launch_bounds__(256) norm_rope_wp(
    const float* __restrict__ x,
    const float* __restrict__ Wwp, const float* __restrict__ bwp,
    const float* __restrict__ wqn, const float* __restrict__ wkn)
{
    int lane = threadIdx.x & 31;
    int tok = blockIdx.x * 8 + (threadIdx.x >> 5);
    const float* row = g_qkv + (size_t)tok * QKVN;

    float qv[8], kv[8];
#pragma unroll
    for (int e = 0; e < 8; e++) {
        qv[e] = row[lane * 8 + e];
        kv[e] = row[256 + lane * 8 + e];
    }
    float sq = 0.f, sk = 0.f;
#pragma unroll
    for (int e = 0; e < 8; e++) { sq += qv[e] * qv[e]; sk += kv[e] * kv[e]; }
#pragma unroll
    for (int off = 1; off < 8; off <<= 1) {
        sq += __shfl_xor_sync(0xffffffffu, sq, off);
        sk += __shfl_xor_sync(0xffffffffu, sk, off);
    }
    float rq = rsqrtf(sq * (1.f / 64.f) + 1e-6f);
    float rk = rsqrtf(sk * (1.f / 64.f) + 1e-6f);

    int h = lane >> 3;     // head index = RoPE position
    int dl = lane & 7;     // lane within head
#pragma unroll
    for (int e = 0; e < 8; e++) {
        int d = dl * 8 + e;
        qv[e] *= rq * wqn[d];
        kv[e] *= rk * wkn[d];
    }
    float sgn = (lane & 4) ? 1.f : -1.f;   // low half: x1*cos - x2*sin ; high: x2*cos + x1*sin
#pragma unroll
    for (int e = 0; e < 8; e++) {
        float qp = __shfl_xor_sync(0xffffffffu, qv[e], 4);
        float kp = __shfl_xor_sync(0xffffffffu, kv[e], 4);
        int f = (lane & 3) * 8 + e;             // freq index 0..31
        float freq = powf(10000.f, -(float)f / 32.f);
        float ang = (float)h * freq;
        float ss, cc;
        __sincosf(ang, &ss, &cc);
        qv[e] = qv[e] * cc + sgn * qp * ss;
        kv[e] = kv[e] * cc + sgn * kp * ss;
    }
#pragma unroll
    for (int e = 0; e < 8; e++) {
        g_q[(size_t)tok * CDIM + lane * 8 + e] = qv[e];
        g_k[(size_t)tok * CDIM + lane * 8 + e] = kv[e];
    }

    // width/sharpness projection: wp = silu(x@W_wp + b_wp), 8 outputs
    const float* xr = x + (size_t)tok * CDIM;
    float xe[8];
#pragma unroll
    for (int e = 0; e < 8; e++) xe[e] = xr[lane * 8 + e];
    float outv[8];
#pragma unroll
    for (int o = 0; o < 8; o++) {
        float p = 0.f;
#pragma unroll
        for (int e = 0; e < 8; e++) p += xe[e] * Wwp[(lane * 8 + e) * 8 + o];
#pragma unroll
        for (int off = 16; off >= 1; off >>= 1) p += __shfl_xor_sync(0xffffffffu, p, off);
        outv[o] = p;
    }
    if (lane < 8) {
        float w = siluf_(outv[lane] + bwp[lane]);
        if (lane < 4) g_width[tok * 4 + lane] = sigmoidf_(w) * MAXDIST + 0.5f;
        else          g_sharp[tok * 4 + lane - 4] = sigmoidf_(w) * 9.5f + 0.5f;
    }
}

// ---------------- local window attention ----------------
// block = (8x8 token tile, batch, head). Halo 14x14 of k/v in smem (stride 65,
// conflict-free for lane-per-window score pass and lane-per-d output pass).
#define HSTRIDE 65
__global__ void __launch_bounds__(256) attn_kernel()
{
    extern __shared__ float sm[];
    float* k_s = sm;                      // 196 * 65
    float* v_s = sm + 196 * HSTRIDE;      // 196 * 65
    float* q_s = v_s + 196 * HSTRIDE;     // 64 * 64

    int tile = blockIdx.x;
    int b = blockIdx.y;
    int h = blockIdx.z;
    int ty0 = (tile >> 3) * 8, tx0 = (tile & 7) * 8;
    int tid = threadIdx.x;

    // halo load: 196 rows x 64 floats for k and v
    for (int idx = tid; idx < 196 * 16; idx += 256) {
        int r = idx >> 4;
        int c4 = (idx & 15) * 4;
        int hy = ty0 + (r / 14) - 3;
        int hx = tx0 + (r % 14) - 3;
        float4 kq = make_float4(0.f, 0.f, 0.f, 0.f);
        float4 vq = make_float4(0.f, 0.f, 0.f, 0.f);
        if (hy >= 0 && hy < 64 && hx >= 0 && hx < 64) {
            int tokg = b * 4096 + hy * 64 + hx;
            kq = *(const float4*)&g_k[(size_t)tokg * CDIM + h * 64 + c4];
            vq = *(const float4*)&g_qkv[(size_t)tokg * QKVN + 512 + h * 64 + c4];
        }
        float* kd = &k_s[r * HSTRIDE + c4];
        kd[0] = kq.x; kd[1] = kq.y; kd[2] = kq.z; kd[3] = kq.w;
        float* vd = &v_s[r * HSTRIDE + c4];
        vd[0] = vq.x; vd[1] = vq.y; vd[2] = vq.z; vd[3] = vq.w;
    }
    // q tile: 64 tokens x 64
    for (int idx = tid; idx < 64 * 16; idx += 256) {
        int t = idx >> 4;
        int c4 = (idx & 15) * 4;
        int tokg = b * 4096 + (ty0 + (t >> 3)) * 64 + (tx0 + (t & 7));
        *(float4*)&q_s[t * 64 + c4] =
            *(const float4*)&g_q[(size_t)tokg * CDIM + h * 64 + c4];
    }
    __syncthreads();

    int warpId = tid >> 5, lane = tid & 31;
    int w1 = lane, w2 = lane + 32;
    bool has2 = (w2 < 49);
    int off1 = (w1 / 7) * 14 + (w1 % 7);
    int off2 = has2 ? (w2 / 7) * 14 + (w2 % 7) : 0;
    float di1 = (float)(w1 / 7 - 3), dj1 = (float)(w1 % 7 - 3);
    float rd1 = sqrtf(di1 * di1 + dj1 * dj1);
    float di2 = (float)(w2 / 7 - 3), dj2 = (float)(w2 % 7 - 3);
    float rd2 = sqrtf(di2 * di2 + dj2 * dj2);

    for (int t = 0; t < 8; t++) {
        int ly = warpId, lx = t;
        int base = ly * 14 + lx;
        const float* qp = &q_s[(warpId * 8 + t) * 64];
        const float* k1p = &k_s[(base + off1) * HSTRIDE];
        const float* k2p = &k_s[(base + off2) * HSTRIDE];
        float s1 = 0.f, s2 = 0.f;
#pragma unroll
        for (int d = 0; d < 64; d++) {
            float qd = qp[d];
            s1 += qd * k1p[d];
            s2 += qd * k2p[d];
        }
        int tokg = b * 4096 + (ty0 + ly) * 64 + (tx0 + lx);
        float width = g_width[tokg * NHEAD + h];
        float sharp = g_sharp[tokg * NHEAD + h];
        float m1 = s1 * 0.125f - (1.f - sigmoidf_((width - rd1) * sharp)) * 10000.f;
        float m2 = has2
                   ? s2 * 0.125f - (1.f - sigmoidf_((width - rd2) * sharp)) * 10000.f
                   : -1e30f;
        float mx = fmaxf(m1, m2);
#pragma unroll
        for (int off = 16; off >= 1; off >>= 1)
            mx = fmaxf(mx, __shfl_xor_sync(0xffffffffu, mx, off));
        float e1 = __expf(m1 - mx);
        float e2 = has2 ? __expf(m2 - mx) : 0.f;
        float ssum = e1 + e2;
#pragma unroll
        for (int off = 16; off >= 1; off >>= 1)
            ssum += __shfl_xor_sync(0xffffffffu, ssum, off);
        float inv = 1.f / ssum;
        float a1 = e1 * inv, a2 = e2 * inv;

        float o1 = 0.f, o2 = 0.f;
#pragma unroll
        for (int w = 0; w < 49; w++) {
            float a = (w < 32) ? __shfl_sync(0xffffffffu, a1, w)
                               : __shfl_sync(0xffffffffu, a2, w - 32);
            int vrow = base + (w / 7) * 14 + (w % 7);
            o1 += a * v_s[vrow * HSTRIDE + lane];
            o2 += a * v_s[vrow * HSTRIDE + lane + 32];
        }
        g_att[(size_t)tokg * CDIM + h * 64 + lane] = o1;
        g_att[(size_t)tokg * CDIM + h * 64 + lane + 32] = o2;
    }
}

// ---------------- per-token inverse rms of attention output ----------------
__global__ void __launch_bounds__(256) rmsinv_kernel()
{
    int lane = threadIdx.x & 31;
    int tok = blockIdx.x * 8 + (threadIdx.x >> 5);
    const float4* row = (const float4*)(g_att + (size_t)tok * CDIM);
    float s = 0.f;
#pragma unroll
    for (int i = 0; i < 2; i++) {
        float4 v = row[lane + i * 32];
        s += v.x * v.x + v.y * v.y + v.z * v.z + v.w * v.w;
    }
#pragma unroll
    for (int off = 16; off >= 1; off >>= 1) s += __shfl_xor_sync(0xffffffffu, s, off);
    if (lane == 0) g_rmsinv[tok] = rsqrtf(s * (1.f / 256.f) + 1e-6f);
}

// ---------------- launch ----------------
extern "C" void kernel_launch(void* const* d_in, const int* in_sizes, int n_in,
                              void* d_out, int out_size)
{
    const float* x       = (const float*)d_in[0];
    const float* W_qkv   = (const float*)d_in[1];
    const float* w_qnorm = (const float*)d_in[2];
    const float* w_knorm = (const float*)d_in[3];
    const float* W_wp    = (const float*)d_in[4];
    const float* b_wp    = (const float*)d_in[5];
    const float* w_onorm = (const float*)d_in[6];
    const float* W_out   = (const float*)d_in[7];
    const float* W_gate  = (const float*)d_in[8];
    const float* b_gate  = (const float*)d_in[9];
    float* out = (float*)d_out;

    float *p_qkv, *p_merged;
    cudaGetSymbolAddress((void**)&p_qkv, g_qkv);
    cudaGetSymbolAddress((void**)&p_merged, g_merged);

    // 1) qkv = silu(x @ W_qkv)
    gemm64<0><<<dim3(12, 128), 256>>>(x, 256, W_qkv, 768, p_qkv, 768, nullptr, nullptr);

    // 2) rmsnorm + rope (q,k) + width/sharp projection
    norm_rope_wp<<<1024, 256>>>(x, W_wp, b_wp, w_qnorm, w_knorm);

    // 3) local attention
    size_t smem = (size_t)(196 * HSTRIDE * 2 + 64 * 64) * sizeof(float);
    cudaFuncSetAttribute(attn_kernel, cudaFuncAttributeMaxDynamicSharedMemorySize, (int)smem);
    attn_kernel<<<dim3(64, 2, 4), 256, smem>>>();

    // 4) per-token rms of attention output
    rmsinv_kernel<<<1024, 256>>>();

    // 5) gate GEMM + fused rmsnorm-scale + gate-merge
    gemm64<1><<<dim3(4, 128), 256>>>(p_qkv + 512, 768, W_gate, 256, p_merged, 256,
                                     b_gate, w_onorm);

    // 6) out = silu(merged @ W_out)
    gemm64<0><<<dim3(4, 128), 256>>>(p_merged, 256, W_out, 256, out, 256,
                                     nullptr, nullptr);
}

// round 2
// speedup vs baseline: 1.2381x; 1.2381x over previous
#include <cuda_runtime.h>
#include <cuda_bf16.h>
#include <mma.h>
#include <math.h>

using namespace nvcuda;

#define NTOK 8192
#define CDIM 256
#define NHEAD 4
#define HD 64
#define QKVN 768
#define MAXDIST 4.242640687119285f  /* sqrt(18) */

// ---------------- scratch (no cudaMalloc allowed) ----------------
__device__ float g_qkv[NTOK * QKVN];      // silu(x@W_qkv)  (q|k|v)
__device__ float g_q[NTOK * CDIM];        // normed+roped q
__device__ float g_k[NTOK * CDIM];        // normed+roped k
__device__ float g_att[NTOK * CDIM];      // attention output (pre-rmsnorm)
__device__ float g_merged[NTOK * CDIM];   // gate-merged
__device__ float g_width[NTOK * NHEAD];
__device__ float g_sharp[NTOK * NHEAD];
__device__ float g_rmsinv[NTOK];

__device__ __forceinline__ float sigmoidf_(float x) { return 1.f / (1.f + __expf(-x)); }
__device__ __forceinline__ float siluf_(float x) { return x * sigmoidf_(x); }

__device__ __forceinline__ void split_bf16(float f, __nv_bfloat16& hi, __nv_bfloat16& lo) {
    hi = __float2bfloat16(f);
    lo = __float2bfloat16(f - __bfloat162float(hi));
}

// ---------------- tensor-core GEMM: 128x64 block tile, split-bf16 (3 HMMA) ----------------
// C[M,N] = epi(A[M,K=256] @ B[256,N]); 256 threads = 8 warps (4x2), 32x32 warp tile.
// EPI 0: C = silu(acc)
// EPI 1: gate-merge: g = sigmoid(silu(acc + bias[c]));
//        C = g * A[r,c] + (1-g) * (g_att[r,c] * g_rmsinv[r] * wonorm[c])
#define A_LD 40
#define B_LD 72
#define C_LD 36

template <int EPI>
__global__ void __launch_bounds__(256) gemm_mma(
    const float* __restrict__ A, int lda,
    const float* __restrict__ B, int ldb,
    float* __restrict__ Cmat, int ldc,
    const float* __restrict__ bias,
    const float* __restrict__ wonorm)
{
    // union: [A hi/lo tiles | B hi/lo tiles] vs epilogue C scratch
    __shared__ __align__(16) unsigned char smraw[36992];
    __nv_bfloat16 (*As)[128][A_LD] = (__nv_bfloat16(*)[128][A_LD])smraw;            // [2][128][40]
    __nv_bfloat16 (*Bs)[32][B_LD]  = (__nv_bfloat16(*)[32][B_LD])(smraw + 2 * 128 * A_LD * 2);
    float (*Cs)[32][C_LD]          = (float(*)[32][C_LD])smraw;                      // [8][32][36]

    int tid = threadIdx.x;
    int warp = tid >> 5, lane = tid & 31;
    int wm = warp >> 1, wn = warp & 1;
    int rowBase = blockIdx.y * 128;
    int colBase = blockIdx.x * 64;

    wmma::fragment<wmma::accumulator, 16, 16, 16, float> cf[2][2];
#pragma unroll
    for (int i = 0; i < 2; i++)
#pragma unroll
        for (int j = 0; j < 2; j++) wmma::fill_fragment(cf[i][j], 0.f);

    int ar = tid >> 3, ac4 = (tid & 7) * 4;

    for (int kt = 0; kt < 256; kt += 32) {
        // stage global loads in registers
        float4 av[4], bv[2];
#pragma unroll
        for (int p = 0; p < 4; p++)
            av[p] = *(const float4*)(A + (size_t)(rowBase + ar + p * 32) * lda + kt + ac4);
#pragma unroll
        for (int p = 0; p < 2; p++) {
            int idx = tid + p * 256;
            bv[p] = *(const float4*)(B + (size_t)(kt + (idx >> 4)) * ldb + colBase + (idx & 15) * 4);
        }
        __syncthreads();
#pragma unroll
        for (int p = 0; p < 4; p++) {
            int r = ar + p * 32;
            float e[4] = {av[p].x, av[p].y, av[p].z, av[p].w};
#pragma unroll
            for (int q = 0; q < 4; q++) {
                __nv_bfloat16 hi, lo;
                split_bf16(e[q], hi, lo);
                As[0][r][ac4 + q] = hi;
                As[1][r][ac4 + q] = lo;
            }
        }
#pragma unroll
        for (int p = 0; p < 2; p++) {
            int idx = tid + p * 256;
            int r = idx >> 4, c4 = (idx & 15) * 4;
            float e[4] = {bv[p].x, bv[p].y, bv[p].z, bv[p].w};
#pragma unroll
            for (int q = 0; q < 4; q++) {
                __nv_bfloat16 hi, lo;
                split_bf16(e[q], hi, lo);
                Bs[0][r][c4 + q] = hi;
                Bs[1][r][c4 + q] = lo;
            }
        }
        __syncthreads();

#pragma unroll
        for (int ks = 0; ks < 32; ks += 16) {
            wmma::fragment<wmma::matrix_a, 16, 16, 16, __nv_bfloat16, wmma::row_major> ah[2], al[2];
            wmma::fragment<wmma::matrix_b, 16, 16, 16, __nv_bfloat16, wmma::row_major> bh[2], bl[2];
#pragma unroll
            for (int i = 0; i < 2; i++) {
                wmma::load_matrix_sync(ah[i], &As[0][wm * 32 + i * 16][ks], A_LD);
                wmma::load_matrix_sync(al[i], &As[1][wm * 32 + i * 16][ks], A_LD);
            }
#pragma unroll
            for (int j = 0; j < 2; j++) {
                wmma::load_matrix_sync(bh[j], &Bs[0][ks][wn * 32 + j * 16], B_LD);
                wmma::load_matrix_sync(bl[j], &Bs[1][ks][wn * 32 + j * 16], B_LD);
            }
#pragma unroll
            for (int i = 0; i < 2; i++)
#pragma unroll
                for (int j = 0; j < 2; j++) {
                    wmma::mma_sync(cf[i][j], ah[i], bh[j], cf[i][j]);
                    wmma::mma_sync(cf[i][j], ah[i], bl[j], cf[i][j]);
                    wmma::mma_sync(cf[i][j], al[i], bh[j], cf[i][j]);
                }
        }
    }

    __syncthreads();   // Cs aliases As/Bs
#pragma unroll
    for (int i = 0; i < 2; i++)
#pragma unroll
        for (int j = 0; j < 2; j++)
            wmma::store_matrix_sync(&Cs[warp][i * 16][j * 16], cf[i][j], C_LD, wmma::mem_row_major);
    __syncwarp();

#pragma unroll 4
    for (int rr = 0; rr < 32; rr++) {
        int r = rowBase + wm * 32 + rr;
        int c = colBase + wn * 32 + lane;
        float val = Cs[warp][rr][lane];
        if (EPI == 0) {
            Cmat[(size_t)r * ldc + c] = siluf_(val);
        } else {
            float t = val + bias[c];
            float g = sigmoidf_(siluf_(t));
            float vv = A[(size_t)r * lda + c];
            float att = g_att[(size_t)r * CDIM + c] * g_rmsinv[r] * wonorm[c];
            Cmat[(size_t)r * ldc + c] = g * vv + (1.f - g) * att;
        }
    }
}

// ---------------- fused rmsnorm + RoPE (pos = head index!) + width/sharp ----------------
// warp per token; lane l holds channels [l*8, l*8+8)
__global__ void __launch_bounds__(256) norm_rope_wp(
    const float* __restrict__ x,
    const float* __restrict__ Wwp, const float* __restrict__ bwp,
    const float* __restrict__ wqn, const float* __restrict__ wkn)
{
    int lane = threadIdx.x & 31;
    int tok = blockIdx.x * 8 + (threadIdx.x >> 5);
    const float* row = g_qkv + (size_t)tok * QKVN;

    float qv[8], kv[8];
#pragma unroll
    for (int e = 0; e < 8; e++) {
        qv[e] = row[lane * 8 + e];
        kv[e] = row[256 + lane * 8 + e];
    }
    float sq = 0.f, sk = 0.f;
#pragma unroll
    for (int e = 0; e < 8; e++) { sq += qv[e] * qv[e]; sk += kv[e] * kv[e]; }
#pragma unroll
    for (int off = 1; off < 8; off <<= 1) {
        sq += __shfl_xor_sync(0xffffffffu, sq, off);
        sk += __shfl_xor_sync(0xffffffffu, sk, off);
    }
    float rq = rsqrtf(sq * (1.f / 64.f) + 1e-6f);
    float rk = rsqrtf(sk * (1.f / 64.f) + 1e-6f);

    int h = lane >> 3;     // head index = RoPE position
    int dl = lane & 7;     // lane within head
#pragma unroll
    for (int e = 0; e < 8; e++) {
        int d = dl * 8 + e;
        qv[e] *= rq * wqn[d];
        kv[e] *= rk * wkn[d];
    }
    float sgn = (lane & 4) ? 1.f : -1.f;
#pragma unroll
    for (int e = 0; e < 8; e++) {
        float qp = __shfl_xor_sync(0xffffffffu, qv[e], 4);
        float kp = __shfl_xor_sync(0xffffffffu, kv[e], 4);
        int f = (lane & 3) * 8 + e;             // freq index 0..31
        float freq = exp2f(-(float)f * (13.287712379549449f / 32.f));  // 10000^(-f/32)
        float ang = (float)h * freq;
        float ss, cc;
        __sincosf(ang, &ss, &cc);
        qv[e] = qv[e] * cc + sgn * qp * ss;
        kv[e] = kv[e] * cc + sgn * kp * ss;
    }
#pragma unroll
    for (int e = 0; e < 8; e++) {
        g_q[(size_t)tok * CDIM + lane * 8 + e] = qv[e];
        g_k[(size_t)tok * CDIM + lane * 8 + e] = kv[e];
    }

    // width/sharpness projection: wp = silu(x@W_wp + b_wp), 8 outputs
    const float* xr = x + (size_t)tok * CDIM;
    float xe[8];
#pragma unroll
    for (int e = 0; e < 8; e++) xe[e] = xr[lane * 8 + e];
    float outv[8];
#pragma unroll
    for (int o = 0; o < 8; o++) {
        float p = 0.f;
#pragma unroll
        for (int e = 0; e < 8; e++) p += xe[e] * Wwp[(lane * 8 + e) * 8 + o];
#pragma unroll
        for (int off = 16; off >= 1; off >>= 1) p += __shfl_xor_sync(0xffffffffu, p, off);
        outv[o] = p;
    }
    if (lane < 8) {
        float w = siluf_(outv[lane] + bwp[lane]);
        if (lane < 4) g_width[tok * 4 + lane] = sigmoidf_(w) * MAXDIST + 0.5f;
        else          g_sharp[tok * 4 + lane - 4] = sigmoidf_(w) * 9.5f + 0.5f;
    }
}

// ---------------- local window attention ----------------
#define HSTRIDE 65
__global__ void __launch_bounds__(256) attn_kernel()
{
    extern __shared__ float sm[];
    float* k_s = sm;                      // 196 * 65
    float* v_s = sm + 196 * HSTRIDE;      // 196 * 65
    float* q_s = v_s + 196 * HSTRIDE;     // 64 * 64

    int tile = blockIdx.x;
    int b = blockIdx.y;
    int h = blockIdx.z;
    int ty0 = (tile >> 3) * 8, tx0 = (tile & 7) * 8;
    int tid = threadIdx.x;

    for (int idx = tid; idx < 196 * 16; idx += 256) {
        int r = idx >> 4;
        int c4 = (idx & 15) * 4;
        int hy = ty0 + (r / 14) - 3;
        int hx = tx0 + (r % 14) - 3;
        float4 kq = make_float4(0.f, 0.f, 0.f, 0.f);
        float4 vq = make_float4(0.f, 0.f, 0.f, 0.f);
        if (hy >= 0 && hy < 64 && hx >= 0 && hx < 64) {
            int tokg = b * 4096 + hy * 64 + hx;
            kq = *(const float4*)&g_k[(size_t)tokg * CDIM + h * 64 + c4];
            vq = *(const float4*)&g_qkv[(size_t)tokg * QKVN + 512 + h * 64 + c4];
        }
        float* kd = &k_s[r * HSTRIDE + c4];
        kd[0] = kq.x; kd[1] = kq.y; kd[2] = kq.z; kd[3] = kq.w;
        float* vd = &v_s[r * HSTRIDE + c4];
        vd[0] = vq.x; vd[1] = vq.y; vd[2] = vq.z; vd[3] = vq.w;
    }
    for (int idx = tid; idx < 64 * 16; idx += 256) {
        int t = idx >> 4;
        int c4 = (idx & 15) * 4;
        int tokg = b * 4096 + (ty0 + (t >> 3)) * 64 + (tx0 + (t & 7));
        *(float4*)&q_s[t * 64 + c4] =
            *(const float4*)&g_q[(size_t)tokg * CDIM + h * 64 + c4];
    }
    __syncthreads();

    int warpId = tid >> 5, lane = tid & 31;
    int w1 = lane, w2 = lane + 32;
    bool has2 = (w2 < 49);
    int off1 = (w1 / 7) * 14 + (w1 % 7);
    int off2 = has2 ? (w2 / 7) * 14 + (w2 % 7) : 0;
    float di1 = (float)(w1 / 7 - 3), dj1 = (float)(w1 % 7 - 3);
    float rd1 = sqrtf(di1 * di1 + dj1 * dj1);
    float di2 = (float)(w2 / 7 - 3), dj2 = (float)(w2 % 7 - 3);
    float rd2 = sqrtf(di2 * di2 + dj2 * dj2);

    for (int t = 0; t < 8; t++) {
        int ly = warpId, lx = t;
        int base = ly * 14 + lx;
        const float* qp = &q_s[(warpId * 8 + t) * 64];
        const float* k1p = &k_s[(base + off1) * HSTRIDE];
        const float* k2p = &k_s[(base + off2) * HSTRIDE];
        float s1 = 0.f, s2 = 0.f;
#pragma unroll
        for (int d = 0; d < 64; d++) {
            float qd = qp[d];
            s1 += qd * k1p[d];
            s2 += qd * k2p[d];
        }
        int tokg = b * 4096 + (ty0 + ly) * 64 + (tx0 + lx);
        float width = g_width[tokg * NHEAD + h];
        float sharp = g_sharp[tokg * NHEAD + h];
        float m1 = s1 * 0.125f - (1.f - sigmoidf_((width - rd1) * sharp)) * 10000.f;
        float m2 = has2
                   ? s2 * 0.125f - (1.f - sigmoidf_((width - rd2) * sharp)) * 10000.f
                   : -1e30f;
        float mx = fmaxf(m1, m2);
#pragma unroll
        for (int off = 16; off >= 1; off >>= 1)
            mx = fmaxf(mx, __shfl_xor_sync(0xffffffffu, mx, off));
        float e1 = __expf(m1 - mx);
        float e2 = has2 ? __expf(m2 - mx) : 0.f;
        float ssum = e1 + e2;
#pragma unroll
        for (int off = 16; off >= 1; off >>= 1)
            ssum += __shfl_xor_sync(0xffffffffu, ssum, off);
        float inv = 1.f / ssum;
        float a1 = e1 * inv, a2 = e2 * inv;

        float o1 = 0.f, o2 = 0.f;
#pragma unroll
        for (int w = 0; w < 49; w++) {
            float a = (w < 32) ? __shfl_sync(0xffffffffu, a1, w)
                               : __shfl_sync(0xffffffffu, a2, w - 32);
            int vrow = base + (w / 7) * 14 + (w % 7);
            o1 += a * v_s[vrow * HSTRIDE + lane];
            o2 += a * v_s[vrow * HSTRIDE + lane + 32];
        }
        g_att[(size_t)tokg * CDIM + h * 64 + lane] = o1;
        g_att[(size_t)tokg * CDIM + h * 64 + lane + 32] = o2;
    }
}

// ---------------- per-token inverse rms of attention output ----------------
__global__ void __launch_bounds__(256) rmsinv_kernel()
{
    int lane = threadIdx.x & 31;
    int tok = blockIdx.x * 8 + (threadIdx.x >> 5);
    const float4* row = (const float4*)(g_att + (size_t)tok * CDIM);
    float s = 0.f;
#pragma unroll
    for (int i = 0; i < 2; i++) {
        float4 v = row[lane + i * 32];
        s += v.x * v.x + v.y * v.y + v.z * v.z + v.w * v.w;
    }
#pragma unroll
    for (int off = 16; off >= 1; off >>= 1) s += __shfl_xor_sync(0xffffffffu, s, off);
    if (lane == 0) g_rmsinv[tok] = rsqrtf(s * (1.f / 256.f) + 1e-6f);
}

// ---------------- launch ----------------
extern "C" void kernel_launch(void* const* d_in, const int* in_sizes, int n_in,
                              void* d_out, int out_size)
{
    const float* x       = (const float*)d_in[0];
    const float* W_qkv   = (const float*)d_in[1];
    const float* w_qnorm = (const float*)d_in[2];
    const float* w_knorm = (const float*)d_in[3];
    const float* W_wp    = (const float*)d_in[4];
    const float* b_wp    = (const float*)d_in[5];
    const float* w_onorm = (const float*)d_in[6];
    const float* W_out   = (const float*)d_in[7];
    const float* W_gate  = (const float*)d_in[8];
    const float* b_gate  = (const float*)d_in[9];
    float* out = (float*)d_out;

    float *p_qkv, *p_merged;
    cudaGetSymbolAddress((void**)&p_qkv, g_qkv);
    cudaGetSymbolAddress((void**)&p_merged, g_merged);

    // 1) qkv = silu(x @ W_qkv)
    gemm_mma<0><<<dim3(12, 64), 256>>>(x, 256, W_qkv, 768, p_qkv, 768, nullptr, nullptr);

    // 2) rmsnorm + rope (q,k) + width/sharp projection
    norm_rope_wp<<<1024, 256>>>(x, W_wp, b_wp, w_qnorm, w_knorm);

    // 3) local attention
    size_t smem = (size_t)(196 * HSTRIDE * 2 + 64 * 64) * sizeof(float);
    cudaFuncSetAttribute(attn_kernel, cudaFuncAttributeMaxDynamicSharedMemorySize, (int)smem);
    attn_kernel<<<dim3(64, 2, 4), 256, smem>>>();

    // 4) per-token rms of attention output
    rmsinv_kernel<<<1024, 256>>>();

    // 5) gate GEMM + fused rmsnorm-scale + gate-merge
    gemm_mma<1><<<dim3(4, 64), 256>>>(p_qkv + 512, 768, W_gate, 256, p_merged, 256,
                                      b_gate, w_onorm);

    // 6) out = silu(merged @ W_out)
    gemm_mma<0><<<dim3(4, 64), 256>>>(p_merged, 256, W_out, 256, out, 256,
                                      nullptr, nullptr);
}